// round 2
// baseline (speedup 1.0000x reference)
#include <cuda_runtime.h>
#include <cuda_bf16.h>
#include <math.h>

// Problem: Elman RNN LM.
//   input_tensor [16,512] i32 ; emb [32000,1024] ; w_ih [2,1024,1024]
//   w_hh [2,1024,1024] ; b_ih [2,1024] ; b_hh [2,1024]
//   w_out [32000,1024] ; b_out [32000]
//   out = logits[16,512,32000] (flat) ++ h_n[2,16,1024] (flat), fp32
#define BB   16
#define SS   512
#define HH   1024
#define MM   (BB * SS)          // 8192
#define OO   32000
#define NBLK 128                // persistent recurrence grid (<= #SMs)

// Scratch (device globals — no cudaMalloc allowed by harness rules)
__device__ float g_x[MM * HH];      // 32 MB: activations / layer outputs
__device__ float g_pre[MM * HH];    // 32 MB: per-layer input contribution
__device__ unsigned g_bar;          // grid-barrier counter

// ---------------------------------------------------------------------------
// Embedding gather: g_x[m,:] = emb[idx[m],:]  (idx==0 -> zeros, padding_idx)
// ---------------------------------------------------------------------------
__global__ __launch_bounds__(256) void embed_kernel(const int* __restrict__ inp,
                                                    const float* __restrict__ emb) {
    int m = blockIdx.x;
    int idx = inp[m];
    float4 v = make_float4(0.f, 0.f, 0.f, 0.f);
    if (idx != 0)
        v = __ldg((const float4*)&emb[(size_t)idx * HH + threadIdx.x * 4]);
    *(float4*)&g_x[(size_t)m * HH + threadIdx.x * 4] = v;
}

// ---------------------------------------------------------------------------
// fp32 SIMT GEMM:  g_pre[M,1024] = g_x[M,1024] @ W[1024,1024]^T + bias
// BM=BN=128, BK=16, 256 thr, 8x8 micro-tile. Kept full fp32 (feeds recurrence).
// ---------------------------------------------------------------------------
__global__ __launch_bounds__(256) void sgemm_pre(const float* __restrict__ W,
                                                 const float* __restrict__ bias) {
    __shared__ float As[16][132];   // [k][m]
    __shared__ float Ws[16][132];   // [k][n]
    const int tid = threadIdx.x;
    const int tx = tid & 15, ty = tid >> 4;
    const int mBase = blockIdx.y * 128, nBase = blockIdx.x * 128;

    float acc[8][8];
#pragma unroll
    for (int i = 0; i < 8; i++)
#pragma unroll
        for (int j = 0; j < 8; j++) acc[i][j] = 0.f;

    for (int kt = 0; kt < HH / 16; kt++) {
#pragma unroll
        for (int i = 0; i < 2; i++) {
            int f = tid + i * 256;              // 512 float4 per operand tile
            int row = f >> 2, c4 = f & 3;
            float4 av = __ldg((const float4*)&g_x[(size_t)(mBase + row) * HH + kt * 16 + c4 * 4]);
            As[c4 * 4 + 0][row] = av.x; As[c4 * 4 + 1][row] = av.y;
            As[c4 * 4 + 2][row] = av.z; As[c4 * 4 + 3][row] = av.w;
            float4 wv = __ldg((const float4*)&W[(size_t)(nBase + row) * HH + kt * 16 + c4 * 4]);
            Ws[c4 * 4 + 0][row] = wv.x; Ws[c4 * 4 + 1][row] = wv.y;
            Ws[c4 * 4 + 2][row] = wv.z; Ws[c4 * 4 + 3][row] = wv.w;
        }
        __syncthreads();
#pragma unroll
        for (int k = 0; k < 16; k++) {
            float a[8], b[8];
            *(float4*)&a[0] = *(const float4*)&As[k][ty * 8];
            *(float4*)&a[4] = *(const float4*)&As[k][ty * 8 + 4];
            *(float4*)&b[0] = *(const float4*)&Ws[k][tx * 8];
            *(float4*)&b[4] = *(const float4*)&Ws[k][tx * 8 + 4];
#pragma unroll
            for (int i = 0; i < 8; i++)
#pragma unroll
                for (int j = 0; j < 8; j++) acc[i][j] = fmaf(a[i], b[j], acc[i][j]);
        }
        __syncthreads();
    }
    float4 bz0 = __ldg((const float4*)&bias[nBase + tx * 8]);
    float4 bz1 = __ldg((const float4*)&bias[nBase + tx * 8 + 4]);
#pragma unroll
    for (int i = 0; i < 8; i++) {
        int row = mBase + ty * 8 + i;
        float4 o0 = make_float4(acc[i][0] + bz0.x, acc[i][1] + bz0.y,
                                acc[i][2] + bz0.z, acc[i][3] + bz0.w);
        float4 o1 = make_float4(acc[i][4] + bz1.x, acc[i][5] + bz1.y,
                                acc[i][6] + bz1.z, acc[i][7] + bz1.w);
        *(float4*)&g_pre[(size_t)row * HH + nBase + tx * 8]     = o0;
        *(float4*)&g_pre[(size_t)row * HH + nBase + tx * 8 + 4] = o1;
    }
}

// ---------------------------------------------------------------------------
// Grid barrier: monotonic counter, reset by reset_bar before each layer.
// ---------------------------------------------------------------------------
__global__ void reset_bar() { g_bar = 0u; }

__device__ __forceinline__ void grid_barrier(unsigned target) {
    __syncthreads();                       // all threads of block done with step
    if (threadIdx.x == 0) {
        __threadfence();                   // release our g_x stores
        atomicAdd(&g_bar, 1u);
        while (*(volatile unsigned*)&g_bar < target) __nanosleep(64);
        __threadfence();                   // acquire others' stores
    }
    __syncthreads();
}

// ---------------------------------------------------------------------------
// Persistent Elman recurrence, one layer:
//   g_x[:,t,:] = tanh(g_pre[:,t,:] + h_{t-1} @ W_hh^T + b_hh)
// 128 blocks x 256 thr. Block owns 8 output columns (W slice pinned in SMEM).
// Warp = 4 batches x 4 cols; lanes split K (1024) into 32-wide chunks.
// ---------------------------------------------------------------------------
__global__ __launch_bounds__(256) void rnn_layer(const float* __restrict__ whh,
                                                 const float* __restrict__ bhh,
                                                 float* __restrict__ hn) {
    extern __shared__ float smem[];
    float* ws = smem;               // [8][1024]  W_hh rows j0..j0+7
    float* hs = smem + 8 * HH;      // [16][1024] h_{t-1}

    const int tid = threadIdx.x, lane = tid & 31, w = tid >> 5;
    const int bg = w & 3;           // batch group (4 batches each)
    const int jg = w >> 2;          // column group (4 cols each)
    const int j0 = blockIdx.x * 8;

    for (int idx = tid; idx < 8 * HH; idx += 256) {
        int j = idx >> 10, k = idx & (HH - 1);
        ws[idx] = whh[(size_t)(j0 + j) * HH + k];
    }

    unsigned target = 0;
    for (int t = 0; t < SS; t++) {
        if (t > 0) { target += NBLK; grid_barrier(target); }

        if (t == 0) {
            float4 z = make_float4(0.f, 0.f, 0.f, 0.f);
#pragma unroll
            for (int i = 0; i < 16; i++) ((float4*)hs)[tid + i * 256] = z;
        } else {
#pragma unroll
            for (int i = 0; i < 16; i++) {
                int f4 = tid + i * 256;
                int l4 = f4 << 2;
                int b = l4 >> 10, k = l4 & (HH - 1);
                ((float4*)hs)[f4] =
                    __ldcg((const float4*)&g_x[((size_t)b * SS + (t - 1)) * HH + k]);
            }
        }
        __syncthreads();

        float acc[16];
#pragma unroll
        for (int r = 0; r < 16; r++) acc[r] = 0.f;

#pragma unroll
        for (int i = 0; i < 8; i++) {
            int k = i * 128 + lane * 4;
            float4 hv[4], wv[4];
#pragma unroll
            for (int b = 0; b < 4; b++) hv[b] = *(const float4*)&hs[(bg * 4 + b) * HH + k];
#pragma unroll
            for (int j = 0; j < 4; j++) wv[j] = *(const float4*)&ws[(jg * 4 + j) * HH + k];
#pragma unroll
            for (int b = 0; b < 4; b++)
#pragma unroll
                for (int j = 0; j < 4; j++) {
                    float s = acc[b * 4 + j];
                    s = fmaf(hv[b].x, wv[j].x, s);
                    s = fmaf(hv[b].y, wv[j].y, s);
                    s = fmaf(hv[b].z, wv[j].z, s);
                    s = fmaf(hv[b].w, wv[j].w, s);
                    acc[b * 4 + j] = s;
                }
        }
#pragma unroll
        for (int r = 0; r < 16; r++) {
            float v = acc[r];
#pragma unroll
            for (int o = 16; o > 0; o >>= 1) v += __shfl_xor_sync(0xffffffffu, v, o);
            acc[r] = v;
        }
        if (lane < 16) {
            float sum = acc[0];
#pragma unroll
            for (int r = 1; r < 16; r++)
                if (lane == r) sum = acc[r];
            int b = bg * 4 + (lane >> 2);
            int j = j0 + jg * 4 + (lane & 3);
            float v = tanhf(sum + __ldg(&g_pre[((size_t)b * SS + t) * HH + j]) + __ldg(&bhh[j]));
            __stcg(&g_x[((size_t)b * SS + t) * HH + j], v);
            if (t == SS - 1) hn[(size_t)b * HH + j] = v;
        }
        // hs reuse at t+1 is gated by grid_barrier's __syncthreads
    }
}

// ---------------------------------------------------------------------------
// Output GEMM (tf32 tensor path):
//   out[8192,32000] = g_x @ w_out^T + b_out
// mma.sync.m16n8k8.row.col.tf32, BM=BN=128, BK=16, 8 warps (2x4), 64x32/warp.
// SMEM stride 136 -> conflict-free fragment LDS (bank = 8*tg + g + const).
// Grid: x = m-tile (64), y = n-tile (250) so a wave reuses W n-tiles via L2
// and streams W (128 MB) from DRAM only once.
// ---------------------------------------------------------------------------
__device__ __forceinline__ unsigned to_tf32(float v) {
    unsigned u;
    asm("cvt.rna.tf32.f32 %0, %1;" : "=r"(u) : "f"(v));
    return u;
}

__global__ __launch_bounds__(256) void out_gemm(const float* __restrict__ W,
                                                const float* __restrict__ bias,
                                                float* __restrict__ out) {
    __shared__ unsigned As[16][136];   // [k][m], tf32 bits
    __shared__ unsigned Bs[16][136];   // [k][n], tf32 bits
    const int tid = threadIdx.x;
    const int warp = tid >> 5, lane = tid & 31;
    const int wm = warp >> 2;          // 0..1 : 64 M-rows per warp
    const int wn = warp & 3;           // 0..3 : 32 N-cols per warp
    const int g = lane >> 2, tg = lane & 3;
    const int mBase = blockIdx.x * 128, nBase = blockIdx.y * 128;

    float acc[4][4][4];
#pragma unroll
    for (int mi = 0; mi < 4; mi++)
#pragma unroll
        for (int ni = 0; ni < 4; ni++)
#pragma unroll
            for (int q = 0; q < 4; q++) acc[mi][ni][q] = 0.f;

    for (int kt = 0; kt < HH / 16; kt++) {
#pragma unroll
        for (int i = 0; i < 2; i++) {
            int f = tid + i * 256;              // 512 float4 per operand tile
            int row = f >> 2, c4 = f & 3;
            float4 av = __ldg((const float4*)&g_x[(size_t)(mBase + row) * HH + kt * 16 + c4 * 4]);
            As[c4 * 4 + 0][row] = to_tf32(av.x); As[c4 * 4 + 1][row] = to_tf32(av.y);
            As[c4 * 4 + 2][row] = to_tf32(av.z); As[c4 * 4 + 3][row] = to_tf32(av.w);
            float4 wv = __ldg((const float4*)&W[(size_t)(nBase + row) * HH + kt * 16 + c4 * 4]);
            Bs[c4 * 4 + 0][row] = to_tf32(wv.x); Bs[c4 * 4 + 1][row] = to_tf32(wv.y);
            Bs[c4 * 4 + 2][row] = to_tf32(wv.z); Bs[c4 * 4 + 3][row] = to_tf32(wv.w);
        }
        __syncthreads();

#pragma unroll
        for (int ks = 0; ks < 2; ks++) {
            const int k0 = ks * 8;
            unsigned a[4][4], b[4][2];
#pragma unroll
            for (int mi = 0; mi < 4; mi++) {
                int m0 = wm * 64 + mi * 16;
                a[mi][0] = As[k0 + tg    ][m0 + g];
                a[mi][1] = As[k0 + tg    ][m0 + g + 8];
                a[mi][2] = As[k0 + tg + 4][m0 + g];
                a[mi][3] = As[k0 + tg + 4][m0 + g + 8];
            }
#pragma unroll
            for (int ni = 0; ni < 4; ni++) {
                int n0 = wn * 32 + ni * 8;
                b[ni][0] = Bs[k0 + tg    ][n0 + g];
                b[ni][1] = Bs[k0 + tg + 4][n0 + g];
            }
#pragma unroll
            for (int mi = 0; mi < 4; mi++)
#pragma unroll
                for (int ni = 0; ni < 4; ni++) {
                    asm volatile(
                        "mma.sync.aligned.m16n8k8.row.col.f32.tf32.tf32.f32 "
                        "{%0,%1,%2,%3}, {%4,%5,%6,%7}, {%8,%9}, {%0,%1,%2,%3};"
                        : "+f"(acc[mi][ni][0]), "+f"(acc[mi][ni][1]),
                          "+f"(acc[mi][ni][2]), "+f"(acc[mi][ni][3])
                        : "r"(a[mi][0]), "r"(a[mi][1]), "r"(a[mi][2]), "r"(a[mi][3]),
                          "r"(b[ni][0]), "r"(b[ni][1]));
                }
        }
        __syncthreads();
    }

    // Epilogue: +bias, write. c0/c1 are cols (2*tg, 2*tg+1): float2 store.
#pragma unroll
    for (int ni = 0; ni < 4; ni++) {
        int col = nBase + wn * 32 + ni * 8 + tg * 2;
        float bz0 = __ldg(&bias[col]), bz1 = __ldg(&bias[col + 1]);
#pragma unroll
        for (int mi = 0; mi < 4; mi++) {
            int row0 = mBase + wm * 64 + mi * 16 + g;
            float2 v0 = make_float2(acc[mi][ni][0] + bz0, acc[mi][ni][1] + bz1);
            float2 v1 = make_float2(acc[mi][ni][2] + bz0, acc[mi][ni][3] + bz1);
            *(float2*)&out[(size_t)row0 * OO + col]       = v0;
            *(float2*)&out[(size_t)(row0 + 8) * OO + col] = v1;
        }
    }
}

// ---------------------------------------------------------------------------
// Launch
// ---------------------------------------------------------------------------
extern "C" void kernel_launch(void* const* d_in, const int* in_sizes, int n_in,
                              void* d_out, int out_size) {
    const int*   inp   = (const int*)  d_in[0];
    const float* emb   = (const float*)d_in[1];
    const float* w_ih  = (const float*)d_in[2];
    const float* w_hh  = (const float*)d_in[3];
    const float* b_ih  = (const float*)d_in[4];
    const float* b_hh  = (const float*)d_in[5];
    const float* w_out = (const float*)d_in[6];
    const float* b_out = (const float*)d_in[7];
    float* out = (float*)d_out;

    const int rnn_smem = (8 * HH + 16 * HH) * (int)sizeof(float);   // 96 KB
    cudaFuncSetAttribute(rnn_layer, cudaFuncAttributeMaxDynamicSharedMemorySize, rnn_smem);

    embed_kernel<<<MM, 256>>>(inp, emb);

    for (int l = 0; l < 2; l++) {
        dim3 gp(HH / 128, MM / 128);          // (8, 64)
        sgemm_pre<<<gp, 256>>>(w_ih + (size_t)l * HH * HH, b_ih + l * HH);
        reset_bar<<<1, 1>>>();
        rnn_layer<<<NBLK, 256, rnn_smem>>>(w_hh + (size_t)l * HH * HH, b_hh + l * HH,
                                           out + (size_t)MM * OO + (size_t)l * BB * HH);
    }

    dim3 go(MM / 128, OO / 128);              // (64, 250): stream W once
    out_gemm<<<go, 256>>>(w_out, b_out, out);
}

// round 7
// speedup vs baseline: 1.0623x; 1.0623x over previous
#include <cuda_runtime.h>
#include <cuda_bf16.h>
#include <cuda_fp16.h>
#include <math.h>

// Problem: Elman RNN LM.
//   input_tensor [16,512] i32 ; emb [32000,1024] ; w_ih [2,1024,1024]
//   w_hh [2,1024,1024] ; b_ih [2,1024] ; b_hh [2,1024]
//   w_out [32000,1024] ; b_out [32000]
//   out = logits[16,512,32000] (flat) ++ h_n[2,16,1024] (flat), fp32
#define BB   16
#define SS   512
#define HH   1024
#define MM   (BB * SS)          // 8192
#define OO   32000
#define RBLK 64                 // persistent recurrence grid (co-resident)

// Scratch (device globals — no cudaMalloc allowed by harness rules)
__device__ float g_x[MM * HH];      // 32 MB: activations / layer outputs
__device__ float g_pre[MM * HH];    // 32 MB: per-layer input contribution
__device__ unsigned g_bar;          // grid-barrier counter

// Bit-cast __half2 -> unsigned (register move; __half2_as_uint doesn't exist)
__device__ __forceinline__ unsigned h2_as_u32(__half2 h) {
    union { __half2 h2; unsigned u; } c;
    c.h2 = h;
    return c.u;
}

// ---------------------------------------------------------------------------
// Embedding gather: g_x[m,:] = emb[idx[m],:]  (idx==0 -> zeros, padding_idx)
// ---------------------------------------------------------------------------
__global__ __launch_bounds__(256) void embed_kernel(const int* __restrict__ inp,
                                                    const float* __restrict__ emb) {
    int m = blockIdx.x;
    int idx = inp[m];
    float4 v = make_float4(0.f, 0.f, 0.f, 0.f);
    if (idx != 0)
        v = __ldg((const float4*)&emb[(size_t)idx * HH + threadIdx.x * 4]);
    *(float4*)&g_x[(size_t)m * HH + threadIdx.x * 4] = v;
}

// ---------------------------------------------------------------------------
// fp32 SIMT GEMM:  g_pre[M,1024] = g_x[M,1024] @ W[1024,1024]^T + bias
// BM=BN=128, BK=16, 256 thr, 8x8 micro-tile. Kept full fp32 (feeds recurrence).
// ---------------------------------------------------------------------------
__global__ __launch_bounds__(256) void sgemm_pre(const float* __restrict__ W,
                                                 const float* __restrict__ bias) {
    __shared__ float As[16][132];   // [k][m]
    __shared__ float Ws[16][132];   // [k][n]
    const int tid = threadIdx.x;
    const int tx = tid & 15, ty = tid >> 4;
    const int mBase = blockIdx.y * 128, nBase = blockIdx.x * 128;

    float acc[8][8];
#pragma unroll
    for (int i = 0; i < 8; i++)
#pragma unroll
        for (int j = 0; j < 8; j++) acc[i][j] = 0.f;

    for (int kt = 0; kt < HH / 16; kt++) {
#pragma unroll
        for (int i = 0; i < 2; i++) {
            int f = tid + i * 256;              // 512 float4 per operand tile
            int row = f >> 2, c4 = f & 3;
            float4 av = __ldg((const float4*)&g_x[(size_t)(mBase + row) * HH + kt * 16 + c4 * 4]);
            As[c4 * 4 + 0][row] = av.x; As[c4 * 4 + 1][row] = av.y;
            As[c4 * 4 + 2][row] = av.z; As[c4 * 4 + 3][row] = av.w;
            float4 wv = __ldg((const float4*)&W[(size_t)(nBase + row) * HH + kt * 16 + c4 * 4]);
            Ws[c4 * 4 + 0][row] = wv.x; Ws[c4 * 4 + 1][row] = wv.y;
            Ws[c4 * 4 + 2][row] = wv.z; Ws[c4 * 4 + 3][row] = wv.w;
        }
        __syncthreads();
#pragma unroll
        for (int k = 0; k < 16; k++) {
            float a[8], b[8];
            *(float4*)&a[0] = *(const float4*)&As[k][ty * 8];
            *(float4*)&a[4] = *(const float4*)&As[k][ty * 8 + 4];
            *(float4*)&b[0] = *(const float4*)&Ws[k][tx * 8];
            *(float4*)&b[4] = *(const float4*)&Ws[k][tx * 8 + 4];
#pragma unroll
            for (int i = 0; i < 8; i++)
#pragma unroll
                for (int j = 0; j < 8; j++) acc[i][j] = fmaf(a[i], b[j], acc[i][j]);
        }
        __syncthreads();
    }
    float4 bz0 = __ldg((const float4*)&bias[nBase + tx * 8]);
    float4 bz1 = __ldg((const float4*)&bias[nBase + tx * 8 + 4]);
#pragma unroll
    for (int i = 0; i < 8; i++) {
        int row = mBase + ty * 8 + i;
        float4 o0 = make_float4(acc[i][0] + bz0.x, acc[i][1] + bz0.y,
                                acc[i][2] + bz0.z, acc[i][3] + bz0.w);
        float4 o1 = make_float4(acc[i][4] + bz1.x, acc[i][5] + bz1.y,
                                acc[i][6] + bz1.z, acc[i][7] + bz1.w);
        *(float4*)&g_pre[(size_t)row * HH + nBase + tx * 8]     = o0;
        *(float4*)&g_pre[(size_t)row * HH + nBase + tx * 8 + 4] = o1;
    }
}

// ---------------------------------------------------------------------------
// Grid barrier: monotonic counter, reset by reset_bar before each layer.
// ---------------------------------------------------------------------------
__global__ void reset_bar() { g_bar = 0u; }

__device__ __forceinline__ void grid_barrier(unsigned target) {
    __syncthreads();                       // block done with step
    if (threadIdx.x == 0) {
        __threadfence();                   // release our g_x stores
        atomicAdd(&g_bar, 1u);
        while (*(volatile unsigned*)&g_bar < target) __nanosleep(32);
        __threadfence();                   // acquire others' stores
    }
    __syncthreads();
}

// ---------------------------------------------------------------------------
// Persistent Elman recurrence, one layer:
//   g_x[:,t,:] = tanh(g_pre[:,t,:] + h_{t-1} @ W_hh^T + b_hh)
// 64 blocks x 512 thr. Block owns 16 output columns (W slice pinned in SMEM).
// Warp = 4 batches x 4 cols; lanes split K (1024) into 32-wide chunks.
// ---------------------------------------------------------------------------
__global__ __launch_bounds__(512) void rnn_layer(const float* __restrict__ whh,
                                                 const float* __restrict__ bhh,
                                                 float* __restrict__ hn) {
    extern __shared__ float smem[];
    float* ws = smem;                // [16][1024]  W_hh rows j0..j0+15
    float* hs = smem + 16 * HH;      // [16][1024]  h_{t-1}

    const int tid = threadIdx.x, lane = tid & 31, w = tid >> 5;   // 16 warps
    const int bg = w & 3;            // batch group (4 batches each)
    const int jg = w >> 2;           // column group (4 cols each, 0..3)
    const int j0 = blockIdx.x * 16;

    for (int idx = tid; idx < 16 * HH; idx += 512) {
        int j = idx >> 10, k = idx & (HH - 1);
        ws[idx] = whh[(size_t)(j0 + j) * HH + k];
    }

    unsigned target = 0;
    for (int t = 0; t < SS; t++) {
        if (t > 0) { target += RBLK; grid_barrier(target); }

        if (t == 0) {
            float4 z = make_float4(0.f, 0.f, 0.f, 0.f);
#pragma unroll
            for (int i = 0; i < 8; i++) ((float4*)hs)[tid + i * 512] = z;
        } else {
#pragma unroll
            for (int i = 0; i < 8; i++) {
                int f4 = tid + i * 512;
                int l4 = f4 << 2;
                int b = l4 >> 10, k = l4 & (HH - 1);
                ((float4*)hs)[f4] =
                    __ldcg((const float4*)&g_x[((size_t)b * SS + (t - 1)) * HH + k]);
            }
        }
        __syncthreads();

        float acc[16];
#pragma unroll
        for (int r = 0; r < 16; r++) acc[r] = 0.f;

#pragma unroll
        for (int i = 0; i < 8; i++) {
            int k = i * 128 + lane * 4;
            float4 hv[4], wv[4];
#pragma unroll
            for (int b = 0; b < 4; b++) hv[b] = *(const float4*)&hs[(bg * 4 + b) * HH + k];
#pragma unroll
            for (int j = 0; j < 4; j++) wv[j] = *(const float4*)&ws[(jg * 4 + j) * HH + k];
#pragma unroll
            for (int b = 0; b < 4; b++)
#pragma unroll
                for (int j = 0; j < 4; j++) {
                    float s = acc[b * 4 + j];
                    s = fmaf(hv[b].x, wv[j].x, s);
                    s = fmaf(hv[b].y, wv[j].y, s);
                    s = fmaf(hv[b].z, wv[j].z, s);
                    s = fmaf(hv[b].w, wv[j].w, s);
                    acc[b * 4 + j] = s;
                }
        }
#pragma unroll
        for (int r = 0; r < 16; r++) {
            float v = acc[r];
#pragma unroll
            for (int o = 16; o > 0; o >>= 1) v += __shfl_xor_sync(0xffffffffu, v, o);
            acc[r] = v;
        }
        if (lane < 16) {
            float sum = acc[0];
#pragma unroll
            for (int r = 1; r < 16; r++)
                if (lane == r) sum = acc[r];
            int b = bg * 4 + (lane >> 2);
            int j = j0 + jg * 4 + (lane & 3);
            float v = tanhf(sum + __ldg(&g_pre[((size_t)b * SS + t) * HH + j]) + __ldg(&bhh[j]));
            __stcg(&g_x[((size_t)b * SS + t) * HH + j], v);
            if (t == SS - 1) hn[(size_t)b * HH + j] = v;
        }
        // hs reuse at t+1 is gated by grid_barrier's __syncthreads
    }
}

// ---------------------------------------------------------------------------
// Output GEMM (fp16 tensor path, f32 accumulate):
//   out[8192,32000] = g_x @ w_out^T + b_out
// mma.sync.m16n8k16.row.col.f32.f16.f16.f32
// BM=BN=128, BK=32, 8 warps (2x4), 64x32 per warp.
// SMEM [row][k] halves, stride 40 -> conflict-free fragment LDS
// (bank = (20*g + tg + const) mod 32, distinct for all 32 lanes).
// Register prefetch of the next K-tile overlaps LDG with MMA.
// Grid: x = m-tile (64), y = n-tile (250): a wave covers all m-tiles of a few
// n-tiles, so A lives in L2 and W (128 MB) streams from DRAM exactly once.
// fp16 has the same 11-bit mantissa as tf32 and all values are in range,
// products are exact into f32 accumulators -> accuracy matches the tf32 path.
// ---------------------------------------------------------------------------
__global__ __launch_bounds__(256) void out_gemm(const float* __restrict__ W,
                                                const float* __restrict__ bias,
                                                float* __restrict__ out) {
    __shared__ __align__(16) __half As[128][40];   // [m][k], 10 KB
    __shared__ __align__(16) __half Bs[128][40];   // [n][k], 10 KB
    const int tid = threadIdx.x;
    const int warp = tid >> 5, lane = tid & 31;
    const int wm = warp >> 2;          // 0..1 : 64 M-rows per warp
    const int wn = warp & 3;           // 0..3 : 32 N-cols per warp
    const int g = lane >> 2, tg = lane & 3;
    const int mBase = blockIdx.x * 128, nBase = blockIdx.y * 128;

    float acc[4][4][4];
#pragma unroll
    for (int mi = 0; mi < 4; mi++)
#pragma unroll
        for (int ni = 0; ni < 4; ni++)
#pragma unroll
            for (int q = 0; q < 4; q++) acc[mi][ni][q] = 0.f;

    // Per-thread loader footprint: 4 float4 per operand per K-tile (BK=32).
    // f = tid + i*256 ; row = f>>3 (8 float4 per 32-float row) ; c4 = f&7.
    uint2 ra[4], rb[4];
#pragma unroll
    for (int i = 0; i < 4; i++) {
        int f = tid + i * 256, row = f >> 3, c4 = f & 7;
        float4 av = __ldg((const float4*)&g_x[(size_t)(mBase + row) * HH + c4 * 4]);
        float4 wv = __ldg((const float4*)&W[(size_t)(nBase + row) * HH + c4 * 4]);
        ra[i] = make_uint2(h2_as_u32(__floats2half2_rn(av.x, av.y)),
                           h2_as_u32(__floats2half2_rn(av.z, av.w)));
        rb[i] = make_uint2(h2_as_u32(__floats2half2_rn(wv.x, wv.y)),
                           h2_as_u32(__floats2half2_rn(wv.z, wv.w)));
    }

    for (int kt = 0; kt < HH / 32; kt++) {
#pragma unroll
        for (int i = 0; i < 4; i++) {
            int f = tid + i * 256, row = f >> 3, c4 = f & 7;
            *(uint2*)&As[row][c4 * 4] = ra[i];
            *(uint2*)&Bs[row][c4 * 4] = rb[i];
        }
        __syncthreads();

        if (kt + 1 < HH / 32) {
            int kOff = (kt + 1) * 32;
#pragma unroll
            for (int i = 0; i < 4; i++) {
                int f = tid + i * 256, row = f >> 3, c4 = f & 7;
                float4 av = __ldg((const float4*)&g_x[(size_t)(mBase + row) * HH + kOff + c4 * 4]);
                float4 wv = __ldg((const float4*)&W[(size_t)(nBase + row) * HH + kOff + c4 * 4]);
                ra[i] = make_uint2(h2_as_u32(__floats2half2_rn(av.x, av.y)),
                                   h2_as_u32(__floats2half2_rn(av.z, av.w)));
                rb[i] = make_uint2(h2_as_u32(__floats2half2_rn(wv.x, wv.y)),
                                   h2_as_u32(__floats2half2_rn(wv.z, wv.w)));
            }
        }

#pragma unroll
        for (int ks = 0; ks < 2; ks++) {
            const int k0 = ks * 16;
            unsigned a[4][4], b[4][2];
#pragma unroll
            for (int mi = 0; mi < 4; mi++) {
                int m0 = wm * 64 + mi * 16;
                a[mi][0] = *(const unsigned*)&As[m0 + g    ][k0 + 2 * tg];
                a[mi][1] = *(const unsigned*)&As[m0 + g + 8][k0 + 2 * tg];
                a[mi][2] = *(const unsigned*)&As[m0 + g    ][k0 + 2 * tg + 8];
                a[mi][3] = *(const unsigned*)&As[m0 + g + 8][k0 + 2 * tg + 8];
            }
#pragma unroll
            for (int ni = 0; ni < 4; ni++) {
                int n0 = wn * 32 + ni * 8;
                b[ni][0] = *(const unsigned*)&Bs[n0 + g][k0 + 2 * tg];
                b[ni][1] = *(const unsigned*)&Bs[n0 + g][k0 + 2 * tg + 8];
            }
#pragma unroll
            for (int mi = 0; mi < 4; mi++)
#pragma unroll
                for (int ni = 0; ni < 4; ni++) {
                    asm volatile(
                        "mma.sync.aligned.m16n8k16.row.col.f32.f16.f16.f32 "
                        "{%0,%1,%2,%3}, {%4,%5,%6,%7}, {%8,%9}, {%0,%1,%2,%3};"
                        : "+f"(acc[mi][ni][0]), "+f"(acc[mi][ni][1]),
                          "+f"(acc[mi][ni][2]), "+f"(acc[mi][ni][3])
                        : "r"(a[mi][0]), "r"(a[mi][1]), "r"(a[mi][2]), "r"(a[mi][3]),
                          "r"(b[ni][0]), "r"(b[ni][1]));
                }
        }
        __syncthreads();
    }

    // Epilogue: +bias, write. (c0,c1) cols (2tg, 2tg+1) rows g / g+8.
#pragma unroll
    for (int ni = 0; ni < 4; ni++) {
        int col = nBase + wn * 32 + ni * 8 + tg * 2;
        float bz0 = __ldg(&bias[col]), bz1 = __ldg(&bias[col + 1]);
#pragma unroll
        for (int mi = 0; mi < 4; mi++) {
            int row0 = mBase + wm * 64 + mi * 16 + g;
            float2 v0 = make_float2(acc[mi][ni][0] + bz0, acc[mi][ni][1] + bz1);
            float2 v1 = make_float2(acc[mi][ni][2] + bz0, acc[mi][ni][3] + bz1);
            *(float2*)&out[(size_t)row0 * OO + col]       = v0;
            *(float2*)&out[(size_t)(row0 + 8) * OO + col] = v1;
        }
    }
}

// ---------------------------------------------------------------------------
// Launch
// ---------------------------------------------------------------------------
extern "C" void kernel_launch(void* const* d_in, const int* in_sizes, int n_in,
                              void* d_out, int out_size) {
    const int*   inp   = (const int*)  d_in[0];
    const float* emb   = (const float*)d_in[1];
    const float* w_ih  = (const float*)d_in[2];
    const float* w_hh  = (const float*)d_in[3];
    const float* b_ih  = (const float*)d_in[4];
    const float* b_hh  = (const float*)d_in[5];
    const float* w_out = (const float*)d_in[6];
    const float* b_out = (const float*)d_in[7];
    float* out = (float*)d_out;

    const int rnn_smem = (16 * HH + 16 * HH) * (int)sizeof(float);   // 128 KB
    cudaFuncSetAttribute(rnn_layer, cudaFuncAttributeMaxDynamicSharedMemorySize, rnn_smem);

    embed_kernel<<<MM, 256>>>(inp, emb);

    for (int l = 0; l < 2; l++) {
        dim3 gp(HH / 128, MM / 128);          // (8, 64)
        sgemm_pre<<<gp, 256>>>(w_ih + (size_t)l * HH * HH, b_ih + l * HH);
        reset_bar<<<1, 1>>>();
        rnn_layer<<<RBLK, 512, rnn_smem>>>(w_hh + (size_t)l * HH * HH, b_hh + l * HH,
                                           out + (size_t)MM * OO + (size_t)l * BB * HH);
    }

    dim3 go(MM / 128, OO / 128);              // (64, 250): stream W once
    out_gemm<<<go, 256>>>(w_out, b_out, out);
}